// round 11
// baseline (speedup 1.0000x reference)
#include <cuda_runtime.h>
#include <cuda_fp16.h>

// ---------------------------------------------------------------------------
// UNetV2 on GB300, hybrid + transposed epilogue:
//  - nb_conv: FMA f32x2, shuffle-staged fp16 gathers, coalesced fp16x2 atomics
//  - epi: HMMA center tap -> smem transpose -> lane=voxel coalesced epilogue
//  - all intermediate/gather buffers fp16 (lat/bot pre-converted off-path)
// ---------------------------------------------------------------------------

#define MAXN 500000
#define NC   32
#define SEG  16384
#define NBK  26
#define BLKSEG 64
#define ASTRIDE ((size_t)(MAXN + 1) * NC)
#define ACCBYTES (ASTRIDE * sizeof(__half))
#define ROWB 80
#define WSPAN (3 * 32 * ROWB)        // x0b | dsm | x1b per warp

static __device__ __half g_acc[4 * ASTRIDE];
static __device__ __half g_h1[MAXN * NC];
static __device__ __half g_h2[MAXN * NC];
static __device__ __half g_h3[MAXN * NC];
static __device__ __half g_hlat[MAXN * NC];
static __device__ __half g_hbot[MAXN * NC];
static __device__ int2   g_rb[NBK * SEG];
static __device__ int    g_kcnt[32];

typedef unsigned long long u64;

__device__ __forceinline__ u64 splat2(float a) {
    u64 r; asm("mov.b64 %0, {%1, %1};" : "=l"(r) : "f"(a)); return r;
}
__device__ __forceinline__ u64 pack2(float a, float b) {
    u64 r; asm("mov.b64 %0, {%1, %2};" : "=l"(r) : "f"(a), "f"(b)); return r;
}
__device__ __forceinline__ void fma2(u64& d, u64 a, u64 b) {
    asm("fma.rn.f32x2 %0, %1, %2, %3;" : "=l"(d) : "l"(a), "l"(b), "l"(d));
}
__device__ __forceinline__ float2 unpack2(u64 a) {
    float2 r; asm("mov.b64 {%0, %1}, %2;" : "=f"(r.x), "=f"(r.y) : "l"(a)); return r;
}
__device__ __forceinline__ unsigned cvt_h2(float lo, float hi) {
    unsigned r;
    asm("cvt.rn.f16x2.f32 %0, %1, %2;" : "=r"(r) : "f"(hi), "f"(lo));
    return r;
}
__device__ __forceinline__ float2 h2f(unsigned u) {
    return __half22float2(*(__half2*)&u);
}
__device__ __forceinline__ void redadd_h2(__half* p, unsigned hv) {
    asm volatile("red.global.add.noftz.f16x2 [%0], %1;" :: "l"(p), "r"(hv) : "memory");
}

// ---------------------------------------------------------------------------
// fp32 -> fp16 dense convert (8 elems/thread)
// ---------------------------------------------------------------------------
__global__ __launch_bounds__(256)
void f32tof16(const float* __restrict__ src, __half* __restrict__ dst, int cnt8)
{
    int i = blockIdx.x * 256 + threadIdx.x;
    if (i >= cnt8) return;
    float4 a = __ldg((const float4*)(src + (size_t)i * 8));
    float4 b = __ldg((const float4*)(src + (size_t)i * 8 + 4));
    uint4 v;
    v.x = cvt_h2(a.x, a.y); v.y = cvt_h2(a.z, a.w);
    v.z = cvt_h2(b.x, b.y); v.w = cvt_h2(b.z, b.w);
    ((uint4*)dst)[i] = v;
}

// ---------------------------------------------------------------------------
// HMMA helpers
// ---------------------------------------------------------------------------
__device__ __forceinline__ void stage_row(char* wbase, int r, const __half* row) {
    const uint4* s = (const uint4*)row;
    int sw = (r >> 3) & 3;
    char* rb = wbase + r * ROWB;
    #pragma unroll
    for (int c = 0; c < 4; ++c)
        *(uint4*)(rb + ((c ^ sw) << 4)) = __ldg(s + c);
}
__device__ __forceinline__ void ldmA(unsigned a[4], const char* wbase, int mt,
                                     int kb, int lane) {
    int r  = mt * 16 + (lane & 15);
    int lc = 2 * kb + (lane >> 4);
    unsigned addr = (unsigned)__cvta_generic_to_shared(
        wbase + r * ROWB + ((lc ^ ((r >> 3) & 3)) << 4));
    asm volatile("ldmatrix.sync.aligned.m8n8.x4.shared.b16 {%0,%1,%2,%3}, [%4];"
                 : "=r"(a[0]), "=r"(a[1]), "=r"(a[2]), "=r"(a[3]) : "r"(addr));
}
__device__ __forceinline__ void mma16816(float d[4], const unsigned a[4],
                                         const unsigned b[2]) {
    asm volatile(
        "mma.sync.aligned.m16n8k16.row.col.f32.f16.f16.f32 "
        "{%0,%1,%2,%3},{%4,%5,%6,%7},{%8,%9},{%0,%1,%2,%3};"
        : "+f"(d[0]), "+f"(d[1]), "+f"(d[2]), "+f"(d[3])
        : "r"(a[0]), "r"(a[1]), "r"(a[2]), "r"(a[3]), "r"(b[0]), "r"(b[1]));
}
__device__ __forceinline__ void buildB(unsigned bf[4][2][2], const float* Wk,
                                       int lane) {
    int g = lane >> 2, t = lane & 3;
    #pragma unroll
    for (int nb = 0; nb < 4; ++nb) {
        int nn = nb * 8 + g;
        #pragma unroll
        for (int kb = 0; kb < 2; ++kb) {
            int k0 = 16 * kb + 2 * t;
            bf[nb][kb][0] = cvt_h2(__ldg(Wk + k0 * 32 + nn),
                                   __ldg(Wk + (k0 + 1) * 32 + nn));
            bf[nb][kb][1] = cvt_h2(__ldg(Wk + (k0 + 8) * 32 + nn),
                                   __ldg(Wk + (k0 + 9) * 32 + nn));
        }
    }
}

// ---------------------------------------------------------------------------
__global__ __launch_bounds__(256)
void build_rb(const int* __restrict__ nbr, int n)
{
    __shared__ int nsh[256 * 27];
    const int tid  = threadIdx.x;
    const int lane = tid & 31;
    const long long base = (long long)blockIdx.x * 256;

    for (int i = tid; i < 256 * 27; i += 256) {
        long long g = base * 27 + i;
        nsh[i] = (g < (long long)n * 27) ? nbr[g] : n;
    }
    __syncthreads();

    const int v = (int)(base + tid);
    const bool live = v < n;

    #pragma unroll 1
    for (int j = 0; j < NBK; ++j) {
        int k = (j < 13) ? j : j + 1;
        int u = nsh[tid * 27 + k];
        bool want = live && ((unsigned)u < (unsigned)n);
        unsigned m = __ballot_sync(0xffffffffu, want);
        int rank = __popc(m & ((1u << lane) - 1));
        int leader = (m != 0u) ? (__ffs(m) - 1) : 0;
        int bp = 0;
        if (m != 0u && lane == leader) bp = atomicAdd(&g_kcnt[j], __popc(m));
        bp = __shfl_sync(0xffffffffu, bp, leader);
        int pos = bp + rank;
        if (want && pos < SEG) g_rb[j * SEG + pos] = make_int2(v, u);
    }
}

// ---------------------------------------------------------------------------
// FMA pair GEMM (nb_conv)
// ---------------------------------------------------------------------------
__device__ __forceinline__ void pair_gemm(const u64* f, const u64* wsp, int p,
                                          float& rA, float& rB)
{
    const ulonglong2* row = (const ulonglong2*)(f + p * 32);
    u64 aE = 0ull, aO = 0ull;
    #pragma unroll
    for (int c2 = 0; c2 < 16; ++c2) {
        ulonglong2 q = row[c2];
        fma2(aE, q.x, wsp[2 * c2]);
        fma2(aO, q.y, wsp[2 * c2 + 1]);
    }
    float2 e = unpack2(aE), o = unpack2(aO);
    rA = e.x + o.x;
    rB = e.y + o.y;
}

// ---------------------------------------------------------------------------
// neighbor taps: fp16 gathers, FMA GEMM, coalesced fp16x2 atomics
// ---------------------------------------------------------------------------
__global__ __launch_bounds__(256)
void nb_conv(const __half* __restrict__ x, const float* __restrict__ W,
             int kstride, int hoff, __half* __restrict__ acc, int n)
{
    __shared__ u64 ft[8 * 512];
    const int j   = blockIdx.x / BLKSEG;
    const int bis = blockIdx.x % BLKSEG;
    const int cnt = g_kcnt[j];
    if (bis * 256 >= cnt) return;

    const int k = (j < 13) ? j : j + 1;
    const float* Wk = W + (size_t)k * kstride + hoff;

    const int lane = threadIdx.x & 31;
    const int warp = threadIdx.x >> 5;

    u64 wsp[32];
    #pragma unroll
    for (int c = 0; c < 32; ++c) wsp[c] = splat2(__ldg(Wk + c * 32 + lane));

    const int eidx = bis * 256 + warp * 32 + lane;
    int2 e = (eidx < cnt) ? __ldg(&g_rb[j * SEG + eidx]) : make_int2(n, 0);

    u64* f = ft + warp * 512;
    #pragma unroll 4
    for (int p = 0; p < 16; ++p) {
        int uA = __shfl_sync(0xffffffffu, e.y, 2 * p);
        int uB = __shfl_sync(0xffffffffu, e.y, 2 * p + 1);
        f[p * 32 + lane] = pack2(__half2float(__ldg(x + (size_t)uA * 32 + lane)),
                                 __half2float(__ldg(x + (size_t)uB * 32 + lane)));
    }
    __syncwarp();

    #pragma unroll 2
    for (int p = 0; p < 16; ++p) {
        float rA, rB;
        pair_gemm(f, wsp, p, rA, rB);
        int vA = __shfl_sync(0xffffffffu, e.x, 2 * p);
        int vB = __shfl_sync(0xffffffffu, e.x, 2 * p + 1);
        float pA = __shfl_xor_sync(0xffffffffu, rA, 1);
        float pB = __shfl_xor_sync(0xffffffffu, rB, 1);
        unsigned hv;
        int v;
        if ((lane & 1) == 0) { hv = cvt_h2(rA, pA); v = vA; }
        else                 { hv = cvt_h2(pB, rB); v = vB; }
        redadd_h2(acc + (size_t)v * 32 + (lane & ~1), hv);
    }
}

// ---------------------------------------------------------------------------
// epilogue: HMMA center tap -> smem transpose -> lane=voxel coalesced epilogue
//  MODE 0: y = relu(bn(acc + Wc0^T x0))
//  MODE 1: y = relu(bn(acc + Wc0^T x0) + res)
//  MODE 2: y = relu(bn(acc + Wc0^T x0 + Wc1^T x1)) + xred(cat(x0,x1))
// ---------------------------------------------------------------------------
template <int MODE, typename TOUT>
__global__ __launch_bounds__(128)
void epi(const __half* __restrict__ acc, const float* __restrict__ bnp,
         const __half* __restrict__ x0, const float* __restrict__ Wc0,
         const __half* __restrict__ x1, const float* __restrict__ Wc1,
         const __half* __restrict__ res,
         TOUT* __restrict__ out, int n)
{
    __shared__ __align__(16) char xsm[4 * WSPAN];
    __shared__ float ssm[32], bsm[32];

    const int tid  = threadIdx.x;
    const int lane = tid & 31;
    const int warp = tid >> 5;
    const int g = lane >> 2, t = lane & 3;

    if (tid < 32) {
        float s = __ldg(bnp + tid) * rsqrtf(__ldg(bnp + 96 + tid) + 1e-3f);
        ssm[tid] = s;
        bsm[tid] = __ldg(bnp + 32 + tid) - __ldg(bnp + 64 + tid) * s;
    }
    __syncthreads();

    const int base = (blockIdx.x * 4 + warp) * 32;
    if (base >= n) return;

    char* x0b = xsm + warp * WSPAN;
    char* dsm = x0b + 32 * ROWB;
    char* x1b = dsm + 32 * ROWB;

    {
        int vox = base + lane;
        int uu = (vox < n) ? vox : 0;
        stage_row(x0b, lane, x0 + (size_t)uu * 32);
        if (MODE == 2) stage_row(x1b, lane, x1 + (size_t)uu * 32);
    }
    __syncwarp();

    unsigned bf0[4][2][2];
    buildB(bf0, Wc0, lane);
    unsigned bf1[4][2][2];
    if (MODE == 2) buildB(bf1, Wc1, lane);

    #pragma unroll
    for (int mt = 0; mt < 2; ++mt) {
        unsigned a0[2][4];
        ldmA(a0[0], x0b, mt, 0, lane);
        ldmA(a0[1], x0b, mt, 1, lane);
        float d[4][4] = {};
        #pragma unroll
        for (int nb = 0; nb < 4; ++nb) {
            mma16816(d[nb], a0[0], bf0[nb][0]);
            mma16816(d[nb], a0[1], bf0[nb][1]);
        }
        if (MODE == 2) {
            unsigned a1[2][4];
            ldmA(a1[0], x1b, mt, 0, lane);
            ldmA(a1[1], x1b, mt, 1, lane);
            #pragma unroll
            for (int nb = 0; nb < 4; ++nb) {
                mma16816(d[nb], a1[0], bf1[nb][0]);
                mma16816(d[nb], a1[1], bf1[nb][1]);
            }
        }
        // spill D to dsm (fp16, swizzled rows; conflict-free within phases)
        #pragma unroll
        for (int rw = 0; rw < 2; ++rw) {
            int r  = mt * 16 + 8 * rw + g;
            int sw = (r >> 3) & 3;
            char* rb = dsm + r * ROWB;
            #pragma unroll
            for (int nb = 0; nb < 4; ++nb)
                *(unsigned*)(rb + ((nb ^ sw) << 4) + 4 * t) =
                    cvt_h2(d[nb][2 * rw], d[nb][2 * rw + 1]);
        }
    }
    __syncwarp();

    // ---- lane = voxel coalesced epilogue ----
    const int v = base + lane;
    if (v >= n) return;

    const int sw = (lane >> 3) & 3;
    const char* drb = dsm + lane * ROWB;
    const char* x0r = x0b + lane * ROWB;
    const char* x1r = x1b + lane * ROWB;

    #pragma unroll
    for (int hf = 0; hf < 2; ++hf) {
        uint4 db0 = *(const uint4*)(drb + (((2 * hf)     ^ sw) << 4));
        uint4 db1 = *(const uint4*)(drb + (((2 * hf + 1) ^ sw) << 4));
        uint4 ab0 = __ldg((const uint4*)(acc + (size_t)v * 32 + 16 * hf));
        uint4 ab1 = __ldg((const uint4*)(acc + (size_t)v * 32 + 16 * hf + 8));
        unsigned dbits[8] = {db0.x, db0.y, db0.z, db0.w, db1.x, db1.y, db1.z, db1.w};
        unsigned abits[8] = {ab0.x, ab0.y, ab0.z, ab0.w, ab1.x, ab1.y, ab1.z, ab1.w};
        unsigned rbits[8];
        if (MODE == 1) {
            uint4 rb0 = __ldg((const uint4*)(res + (size_t)v * 32 + 16 * hf));
            uint4 rb1 = __ldg((const uint4*)(res + (size_t)v * 32 + 16 * hf + 8));
            rbits[0] = rb0.x; rbits[1] = rb0.y; rbits[2] = rb0.z; rbits[3] = rb0.w;
            rbits[4] = rb1.x; rbits[5] = rb1.y; rbits[6] = rb1.z; rbits[7] = rb1.w;
        }
        unsigned xbits[16];
        if (MODE == 2) {
            const char* xr = hf ? x1r : x0r;
            #pragma unroll
            for (int c = 0; c < 4; ++c) {
                uint4 q = *(const uint4*)(xr + ((c ^ sw) << 4));
                xbits[4 * c] = q.x; xbits[4 * c + 1] = q.y;
                xbits[4 * c + 2] = q.z; xbits[4 * c + 3] = q.w;
            }
        }

        float y[16];
        #pragma unroll
        for (int i = 0; i < 8; ++i) {
            float2 dv = h2f(dbits[i]);
            float2 av = h2f(abits[i]);
            float2 sv = ((const float2*)ssm)[8 * hf + i];
            float2 bv = ((const float2*)bsm)[8 * hf + i];
            float y0 = (av.x + dv.x) * sv.x + bv.x;
            float y1 = (av.y + dv.y) * sv.y + bv.y;
            if (MODE == 1) {
                float2 rv = h2f(rbits[i]);
                y0 += rv.x; y1 += rv.y;
            }
            y0 = fmaxf(y0, 0.0f);
            y1 = fmaxf(y1, 0.0f);
            if (MODE == 2) {
                float2 q0 = h2f(xbits[2 * i]);
                float2 q1 = h2f(xbits[2 * i + 1]);
                y0 += q0.x + q0.y;
                y1 += q1.x + q1.y;
            }
            y[2 * i] = y0;
            y[2 * i + 1] = y1;
        }

        if (sizeof(TOUT) == 2) {
            uint4 o0, o1;
            o0.x = cvt_h2(y[0], y[1]);  o0.y = cvt_h2(y[2], y[3]);
            o0.z = cvt_h2(y[4], y[5]);  o0.w = cvt_h2(y[6], y[7]);
            o1.x = cvt_h2(y[8], y[9]);  o1.y = cvt_h2(y[10], y[11]);
            o1.z = cvt_h2(y[12], y[13]); o1.w = cvt_h2(y[14], y[15]);
            *(uint4*)((__half*)out + (size_t)v * 32 + 16 * hf)     = o0;
            *(uint4*)((__half*)out + (size_t)v * 32 + 16 * hf + 8) = o1;
        } else {
            float* op = (float*)out + (size_t)v * 32 + 16 * hf;
            #pragma unroll
            for (int q = 0; q < 4; ++q)
                *(float4*)(op + 4 * q) = make_float4(y[4 * q], y[4 * q + 1],
                                                     y[4 * q + 2], y[4 * q + 3]);
        }
    }
}

// ---------------------------------------------------------------------------
extern "C" void kernel_launch(void* const* d_in, const int* in_sizes, int n_in,
                              void* d_out, int out_size)
{
    const float* lat  = (const float*)d_in[0];
    const float* bot  = (const float*)d_in[1];
    const float* Wt1  = (const float*)d_in[2];
    const float* bnt1 = (const float*)d_in[3];
    const float* Wt2  = (const float*)d_in[4];
    const float* bnt2 = (const float*)d_in[5];
    const float* Wm   = (const float*)d_in[6];
    const float* bnm  = (const float*)d_in[7];
    const float* Wi   = (const float*)d_in[8];
    const float* bni  = (const float*)d_in[9];
    const int*   nbr  = (const int*)d_in[10];

    const int n = in_sizes[0] / NC;

    __half *accb, *h1, *h2, *h3, *hlat, *hbot;
    int* kcnt;
    cudaGetSymbolAddress((void**)&accb, g_acc);
    cudaGetSymbolAddress((void**)&h1, g_h1);
    cudaGetSymbolAddress((void**)&h2, g_h2);
    cudaGetSymbolAddress((void**)&h3, g_h3);
    cudaGetSymbolAddress((void**)&hlat, g_hlat);
    cudaGetSymbolAddress((void**)&hbot, g_hbot);
    cudaGetSymbolAddress((void**)&kcnt, g_kcnt);

    __half* a1 = accb;
    __half* a2 = accb + 1 * ASTRIDE;
    __half* a3 = accb + 2 * ASTRIDE;
    __half* a4 = accb + 3 * ASTRIDE;

    static cudaStream_t s1 = nullptr, s2 = nullptr;
    static cudaEvent_t e0 = nullptr, eB = nullptr, e2 = nullptr, eL = nullptr;
    static cudaEvent_t em1 = nullptr, em2 = nullptr, em3 = nullptr, em4 = nullptr;
    if (!s1) {
        cudaStreamCreateWithFlags(&s1, cudaStreamNonBlocking);
        cudaStreamCreateWithFlags(&s2, cudaStreamNonBlocking);
        cudaEventCreateWithFlags(&e0, cudaEventDisableTiming);
        cudaEventCreateWithFlags(&eB, cudaEventDisableTiming);
        cudaEventCreateWithFlags(&e2, cudaEventDisableTiming);
        cudaEventCreateWithFlags(&eL, cudaEventDisableTiming);
        cudaEventCreateWithFlags(&em1, cudaEventDisableTiming);
        cudaEventCreateWithFlags(&em2, cudaEventDisableTiming);
        cudaEventCreateWithFlags(&em3, cudaEventDisableTiming);
        cudaEventCreateWithFlags(&em4, cudaEventDisableTiming);
    }

    const int gridB = (n + 255) / 256;
    const int gridE = (n + 127) / 128;
    const int gridN = NBK * BLKSEG;
    const int cnt8  = n * NC / 8;
    const int gridF = (cnt8 + 255) / 256;

    cudaMemsetAsync(kcnt, 0, 32 * sizeof(int), 0);
    cudaEventRecord(e0, 0);

    // s1: acc memsets
    cudaStreamWaitEvent(s1, e0, 0);
    cudaMemsetAsync(a1, 0, ACCBYTES, s1); cudaEventRecord(em1, s1);
    cudaMemsetAsync(a3, 0, ACCBYTES, s1); cudaEventRecord(em3, s1);
    cudaMemsetAsync(a2, 0, ACCBYTES, s1); cudaEventRecord(em2, s1);
    cudaMemsetAsync(a4, 0, ACCBYTES, s1); cudaEventRecord(em4, s1);

    // s2: fp16 conversions, then bot-half nb pass
    cudaStreamWaitEvent(s2, e0, 0);
    f32tof16<<<gridF, 256, 0, s2>>>(lat, hlat, cnt8);
    cudaEventRecord(eL, s2);
    f32tof16<<<gridF, 256, 0, s2>>>(bot, hbot, cnt8);

    build_rb<<<gridB, 256>>>(nbr, n);
    cudaEventRecord(eB, 0);

    cudaStreamWaitEvent(s2, eB, 0);
    cudaStreamWaitEvent(s2, em3, 0);
    nb_conv<<<gridN, 256, 0, s2>>>(hbot, Wm, 2048, 0, a3, n);
    cudaEventRecord(e2, s2);

    // conv1
    cudaStreamWaitEvent(0, em1, 0);
    cudaStreamWaitEvent(0, eL, 0);
    nb_conv<<<gridN, 256>>>(hlat, Wt1, 1024, 0, a1, n);
    epi<0, __half><<<gridE, 128>>>(a1, bnt1, hlat, Wt1 + 13 * 1024,
                                   nullptr, nullptr, nullptr, h1, n);

    // conv2 (residual = hlat)
    cudaStreamWaitEvent(0, em2, 0);
    nb_conv<<<gridN, 256>>>(h1, Wt2, 1024, 0, a2, n);
    epi<1, __half><<<gridE, 128>>>(a2, bnt2, h1, Wt2 + 13 * 1024,
                                   nullptr, nullptr, hlat, h2, n);

    // conv_m
    nb_conv<<<gridN, 256>>>(h2, Wm, 2048, 1024, a3, n);
    cudaStreamWaitEvent(0, e2, 0);
    epi<2, __half><<<gridE, 128>>>(a3, bnm, hbot, Wm + 13 * 2048,
                                   h2, Wm + 13 * 2048 + 1024, nullptr, h3, n);

    // conv_inv
    cudaStreamWaitEvent(0, em4, 0);
    nb_conv<<<gridN, 256>>>(h3, Wi, 1024, 0, a4, n);
    epi<0, float><<<gridE, 128>>>(a4, bni, h3, Wi + 13 * 1024,
                                  nullptr, nullptr, nullptr, (float*)d_out, n);
}